// round 1
// baseline (speedup 1.0000x reference)
#include <cuda_runtime.h>
#include <cuda_bf16.h>
#include <math.h>

#define BATCH 512
#define EPS 1e-5f

// ---------------- scratch (no allocations allowed) ----------------
__device__ float g_out1[BATCH * 256 * 24 * 24];  // 302 MB
__device__ float g_out2[BATCH * 128 * 12 * 12];
__device__ float g_out3[BATCH * 64 * 6 * 6];
__device__ float g_fc1[BATCH * 512];
__device__ float g_fc2[BATCH * 256];
__device__ float g_q[BATCH * 64];

// ---------------- block1: conv(1->256,48x48) + BN + ReLU + pool -> [B,256,24,24] ----------------
#define OCB1 32
__global__ void block1_kernel(const float* __restrict__ x, const float* __restrict__ w,
                              const float* __restrict__ cb, const float* __restrict__ gg,
                              const float* __restrict__ bb, const float* __restrict__ mm,
                              const float* __restrict__ vv, float* __restrict__ out) {
    int b = blockIdx.y;
    int oc0 = blockIdx.x * OCB1;
    __shared__ float tile[50 * 50];
    __shared__ float ws[OCB1 * 9];
    __shared__ float sa[OCB1], sc[OCB1];
    int tid = threadIdx.x;

    const float* xb = x + (size_t)b * 48 * 48;
    for (int i = tid; i < 2500; i += blockDim.x) {
        int r = i / 50, c = i % 50;
        float val = 0.f;
        if (r >= 1 && r <= 48 && c >= 1 && c <= 48) val = xb[(r - 1) * 48 + (c - 1)];
        tile[i] = val;
    }
    for (int i = tid; i < OCB1 * 9; i += blockDim.x) ws[i] = w[oc0 * 9 + i];
    if (tid < OCB1) {
        int oc = oc0 + tid;
        float inv = gg[oc] * rsqrtf(vv[oc] + EPS);
        sa[tid] = inv;
        sc[tid] = (cb[oc] - mm[oc]) * inv + bb[oc];
    }
    __syncthreads();

    for (int it = tid; it < 576; it += blockDim.x) {
        int ph = it / 24, pw = it % 24;
        float p[4][4];
#pragma unroll
        for (int i = 0; i < 4; i++)
#pragma unroll
            for (int j = 0; j < 4; j++)
                p[i][j] = tile[(2 * ph + i) * 50 + (2 * pw + j)];
#pragma unroll 4
        for (int oo = 0; oo < OCB1; oo++) {
            float a = sa[oo], cc = sc[oo];
            const float* wk = &ws[oo * 9];
            float w0 = wk[0], w1 = wk[1], w2 = wk[2], w3 = wk[3], w4 = wk[4],
                  w5 = wk[5], w6 = wk[6], w7 = wk[7], w8 = wk[8];
            float mx = -INFINITY;
#pragma unroll
            for (int py = 0; py < 2; py++)
#pragma unroll
                for (int px = 0; px < 2; px++) {
                    float s = p[py + 0][px + 0] * w0 + p[py + 0][px + 1] * w1 + p[py + 0][px + 2] * w2
                            + p[py + 1][px + 0] * w3 + p[py + 1][px + 1] * w4 + p[py + 1][px + 2] * w5
                            + p[py + 2][px + 0] * w6 + p[py + 2][px + 1] * w7 + p[py + 2][px + 2] * w8;
                    float y = fmaxf(fmaf(s, a, cc), 0.f);
                    mx = fmaxf(mx, y);
                }
            out[(((size_t)b * 256 + oc0 + oo) * 24 + ph) * 24 + pw] = mx;
        }
    }
}

// ---------------- generic fused conv(3x3,pad1)+BN+ReLU+pool block ----------------
// PT = pooled outputs per thread per dim (1 or 2). blockDim = OCB * (HOUT/PT)^2.
template <int CIN, int COUT, int HIN, int OCB, int ICB, int PT>
__global__ void conv_block_kernel(const float* __restrict__ in, const float* __restrict__ w,
                                  const float* __restrict__ cb, const float* __restrict__ gg,
                                  const float* __restrict__ bb, const float* __restrict__ mm,
                                  const float* __restrict__ vv, float* __restrict__ out) {
    constexpr int HOUT = HIN / 2;
    constexpr int TW = HIN + 2;
    constexpr int TDIM = HOUT / PT;         // threads per oc per dim
    constexpr int SP = TDIM * TDIM;         // spatial threads per oc
    constexpr int NT = OCB * SP;            // blockDim
    constexpr int PS = 2 * PT + 2;          // patch size

    __shared__ float tile[ICB * TW * TW];
    __shared__ float ws[OCB * ICB * 9];

    int b = blockIdx.y;
    int oc0 = blockIdx.x * OCB;
    int tid = threadIdx.x;
    int oc_local = tid / SP;
    int sp = tid % SP;
    int th = sp / TDIM, tw = sp % TDIM;
    int rbase = th * 2 * PT;
    int cbase = tw * 2 * PT;

    float acc[2 * PT][2 * PT];
#pragma unroll
    for (int i = 0; i < 2 * PT; i++)
#pragma unroll
        for (int j = 0; j < 2 * PT; j++) acc[i][j] = 0.f;

    const float* inb = in + (size_t)b * CIN * HIN * HIN;

    for (int ic0 = 0; ic0 < CIN; ic0 += ICB) {
        // load input tile (zero-padded halo)
        for (int i = tid; i < ICB * TW * TW; i += NT) {
            int ii = i / (TW * TW);
            int rem = i % (TW * TW);
            int r = rem / TW, c = rem % TW;
            float val = 0.f;
            if (r >= 1 && r <= HIN && c >= 1 && c <= HIN)
                val = inb[((size_t)(ic0 + ii) * HIN + (r - 1)) * HIN + (c - 1)];
            tile[i] = val;
        }
        // load weights for this (oc group, ic chunk)
        for (int i = tid; i < OCB * ICB * 9; i += NT) {
            int oo = i / (ICB * 9);
            int rem = i % (ICB * 9);
            int ii = rem / 9, kk = rem % 9;
            ws[i] = w[((size_t)(oc0 + oo) * CIN + (ic0 + ii)) * 9 + kk];
        }
        __syncthreads();

#pragma unroll 2
        for (int ii = 0; ii < ICB; ii++) {
            const float* tp = &tile[ii * TW * TW];
            float patch[PS][PS];
#pragma unroll
            for (int i = 0; i < PS; i++)
#pragma unroll
                for (int j = 0; j < PS; j++)
                    patch[i][j] = tp[(rbase + i) * TW + (cbase + j)];
            const float* wk = &ws[(oc_local * ICB + ii) * 9];
            float w0 = wk[0], w1 = wk[1], w2 = wk[2], w3 = wk[3], w4 = wk[4],
                  w5 = wk[5], w6 = wk[6], w7 = wk[7], w8 = wk[8];
#pragma unroll
            for (int py = 0; py < 2 * PT; py++)
#pragma unroll
                for (int px = 0; px < 2 * PT; px++) {
                    float s = acc[py][px];
                    s = fmaf(patch[py + 0][px + 0], w0, s);
                    s = fmaf(patch[py + 0][px + 1], w1, s);
                    s = fmaf(patch[py + 0][px + 2], w2, s);
                    s = fmaf(patch[py + 1][px + 0], w3, s);
                    s = fmaf(patch[py + 1][px + 1], w4, s);
                    s = fmaf(patch[py + 1][px + 2], w5, s);
                    s = fmaf(patch[py + 2][px + 0], w6, s);
                    s = fmaf(patch[py + 2][px + 1], w7, s);
                    s = fmaf(patch[py + 2][px + 2], w8, s);
                    acc[py][px] = s;
                }
        }
        __syncthreads();
    }

    // epilogue: BN + ReLU + 2x2 maxpool
    int oc = oc0 + oc_local;
    float inv = gg[oc] * rsqrtf(vv[oc] + EPS);
    float bias = (cb[oc] - mm[oc]) * inv + bb[oc];
#pragma unroll
    for (int pp = 0; pp < PT; pp++)
#pragma unroll
        for (int qq = 0; qq < PT; qq++) {
            float v00 = fmaxf(fmaf(acc[2 * pp + 0][2 * qq + 0], inv, bias), 0.f);
            float v01 = fmaxf(fmaf(acc[2 * pp + 0][2 * qq + 1], inv, bias), 0.f);
            float v10 = fmaxf(fmaf(acc[2 * pp + 1][2 * qq + 0], inv, bias), 0.f);
            float v11 = fmaxf(fmaf(acc[2 * pp + 1][2 * qq + 1], inv, bias), 0.f);
            float mx = fmaxf(fmaxf(v00, v01), fmaxf(v10, v11));
            int PH = th * PT + pp, PW = tw * PT + qq;
            out[(((size_t)b * COUT + oc) * HOUT + PH) * HOUT + PW] = mx;
        }
}

// ---------------- generic linear: C[M,N] = A[M,K] @ W[N,K]^T + bias ----------------
__global__ void linear_kernel(const float* __restrict__ A, const float* __restrict__ W,
                              const float* __restrict__ bias, float* __restrict__ C,
                              int M, int N, int K) {
    __shared__ float As[16][16];
    __shared__ float Ws[16][17];
    int row = blockIdx.y * 16 + threadIdx.y;
    int col = blockIdx.x * 16 + threadIdx.x;
    float acc = 0.f;
    for (int k0 = 0; k0 < K; k0 += 16) {
        int ka = k0 + threadIdx.x;
        As[threadIdx.y][threadIdx.x] = (row < M && ka < K) ? A[(size_t)row * K + ka] : 0.f;
        int wr = blockIdx.x * 16 + threadIdx.y;
        Ws[threadIdx.y][threadIdx.x] = (wr < N && ka < K) ? W[(size_t)wr * K + ka] : 0.f;
        __syncthreads();
#pragma unroll
        for (int kk = 0; kk < 16; kk++)
            acc = fmaf(As[threadIdx.y][kk], Ws[threadIdx.x][kk], acc);
        __syncthreads();
    }
    if (row < M && col < N) C[(size_t)row * N + col] = acc + bias[col];
}

// ---------------- attention epilogue: scores, softmax, weighted sum, fc3 ----------------
__global__ void attention_kernel(const float* __restrict__ out3, const float* __restrict__ q,
                                 const float* __restrict__ fc3_w, const float* __restrict__ fc3_b,
                                 float* __restrict__ out) {
    int b = blockIdx.x;
    __shared__ float s3[64 * 36];
    __shared__ float sq[64];
    __shared__ float sc[36];
    __shared__ float sg[64];
    int tid = threadIdx.x;  // 64 threads
    for (int i = tid; i < 64 * 36; i += 64) s3[i] = out3[(size_t)b * 64 * 36 + i];
    sq[tid] = q[(size_t)b * 64 + tid];
    __syncthreads();
    if (tid < 36) {
        float s = 0.f;
#pragma unroll
        for (int c = 0; c < 64; c++) s = fmaf(s3[c * 36 + tid], sq[c], s);
        sc[tid] = s;
    }
    __syncthreads();
    if (tid == 0) {
        float mx = sc[0];
        for (int i = 1; i < 36; i++) mx = fmaxf(mx, sc[i]);
        float sum = 0.f;
        for (int i = 0; i < 36; i++) { float e = expf(sc[i] - mx); sc[i] = e; sum += e; }
        float invs = 1.f / sum;
        for (int i = 0; i < 36; i++) sc[i] *= invs;
    }
    __syncthreads();
    {
        float s = 0.f;
#pragma unroll
        for (int hw = 0; hw < 36; hw++) s = fmaf(s3[tid * 36 + hw], sc[hw], s);
        sg[tid] = s;
    }
    __syncthreads();
    if (tid < 7) {
        float s = fc3_b[tid];
#pragma unroll
        for (int c = 0; c < 64; c++) s = fmaf(sg[c], fc3_w[tid * 64 + c], s);
        out[(size_t)b * 7 + tid] = s;
    }
}

// ---------------- launch ----------------
extern "C" void kernel_launch(void* const* d_in, const int* in_sizes, int n_in,
                              void* d_out, int out_size) {
    const float* x      = (const float*)d_in[0];
    const float* c1w    = (const float*)d_in[1];
    const float* c1b    = (const float*)d_in[2];
    const float* bn1g   = (const float*)d_in[3];
    const float* bn1b   = (const float*)d_in[4];
    const float* bn1m   = (const float*)d_in[5];
    const float* bn1v   = (const float*)d_in[6];
    const float* c2w    = (const float*)d_in[7];
    const float* c2b    = (const float*)d_in[8];
    const float* bn2g   = (const float*)d_in[9];
    const float* bn2b   = (const float*)d_in[10];
    const float* bn2m   = (const float*)d_in[11];
    const float* bn2v   = (const float*)d_in[12];
    const float* c3w    = (const float*)d_in[13];
    const float* c3b    = (const float*)d_in[14];
    const float* bn3g   = (const float*)d_in[15];
    const float* bn3b   = (const float*)d_in[16];
    const float* bn3m   = (const float*)d_in[17];
    const float* bn3v   = (const float*)d_in[18];
    const float* fc1w   = (const float*)d_in[19];
    const float* fc1b   = (const float*)d_in[20];
    const float* fc2w   = (const float*)d_in[21];
    const float* fc2b   = (const float*)d_in[22];
    const float* attw   = (const float*)d_in[23];
    const float* attb   = (const float*)d_in[24];
    const float* fc3w   = (const float*)d_in[25];
    const float* fc3b   = (const float*)d_in[26];
    float* outp = (float*)d_out;

    float *p_out1, *p_out2, *p_out3, *p_fc1, *p_fc2, *p_q;
    cudaGetSymbolAddress((void**)&p_out1, g_out1);
    cudaGetSymbolAddress((void**)&p_out2, g_out2);
    cudaGetSymbolAddress((void**)&p_out3, g_out3);
    cudaGetSymbolAddress((void**)&p_fc1, g_fc1);
    cudaGetSymbolAddress((void**)&p_fc2, g_fc2);
    cudaGetSymbolAddress((void**)&p_q, g_q);

    // block1: [B,1,48,48] -> [B,256,24,24]
    block1_kernel<<<dim3(256 / OCB1, BATCH), 288>>>(x, c1w, c1b, bn1g, bn1b, bn1m, bn1v, p_out1);

    // block2: [B,256,24,24] -> [B,128,12,12]   (OCB=8, ICB=4, PT=2 -> 288 threads)
    conv_block_kernel<256, 128, 24, 8, 4, 2>
        <<<dim3(128 / 8, BATCH), 8 * 36>>>(p_out1, c2w, c2b, bn2g, bn2b, bn2m, bn2v, p_out2);

    // block3: [B,128,12,12] -> [B,64,6,6]      (OCB=8, ICB=8, PT=1 -> 288 threads)
    conv_block_kernel<128, 64, 12, 8, 8, 1>
        <<<dim3(64 / 8, BATCH), 8 * 36>>>(p_out2, c3w, c3b, bn3g, bn3b, bn3m, bn3v, p_out3);

    // fc1: [512,2304] @ [512,2304]^T -> [512,512]
    linear_kernel<<<dim3(512 / 16, BATCH / 16), dim3(16, 16)>>>(p_out3, fc1w, fc1b, p_fc1, BATCH, 512, 2304);
    // fc2: [512,512] @ [256,512]^T -> [512,256]
    linear_kernel<<<dim3(256 / 16, BATCH / 16), dim3(16, 16)>>>(p_fc1, fc2w, fc2b, p_fc2, BATCH, 256, 512);
    // att: [512,256] @ [64,256]^T -> [512,64]
    linear_kernel<<<dim3(64 / 16, BATCH / 16), dim3(16, 16)>>>(p_fc2, attw, attb, p_q, BATCH, 64, 256);

    // attention + fc3 -> [512,7]
    attention_kernel<<<BATCH, 64>>>(p_out3, p_q, fc3w, fc3b, outp);
}